// round 9
// baseline (speedup 1.0000x reference)
#include <cuda_runtime.h>
#include <math.h>
#include <stdint.h>

#define B_TOT   262144
#define THREADS 256
#define SPT     2
#define CTAS    (B_TOT/(THREADS*SPT))   // 512

// ---- shared memory layout (float offsets; H1 in bytes) ----
#define OFF_W1P   0        // 128 rows x 14 pairs (28 floats) = 3584
#define OFF_B1    3584     // 128
#define OFF_W2G   3712     // 128 rows x 128 floats (g1-folded) = 16384
#define OFF_G2C2  20096    // float2[128] = 256 floats
#define OFF_W3G   20352    // 128 rows x 8 floats (g2-folded) = 1024
#define OFF_G3    21376    // 8
#define OFF_C3    21384    // 8
#define H1_BYTE   85568    // 32 chunks x 256 threads x 16B = 131072 B (B-sample h1, fp32)
#define SMEM_BYTES (H1_BYTE + 131072)   // 216640

typedef unsigned long long u64;

static __device__ __forceinline__ u64 pk2(float lo, float hi) {
    u64 r; asm("mov.b64 %0,{%1,%2};" : "=l"(r) : "f"(lo), "f"(hi)); return r;
}
static __device__ __forceinline__ void upk2(u64 v, float &lo, float &hi) {
    asm("mov.b64 {%0,%1},%2;" : "=f"(lo), "=f"(hi) : "l"(v));
}
static __device__ __forceinline__ u64 ffma2(u64 a, u64 b, u64 c) {
    u64 d; asm("fma.rn.f32x2 %0,%1,%2,%3;" : "=l"(d) : "l"(a), "l"(b), "l"(c)); return d;
}
static __device__ __forceinline__ u64 fadd2(u64 a, u64 b) {
    u64 d; asm("add.rn.f32x2 %0,%1,%2;" : "=l"(d) : "l"(a), "l"(b)); return d;
}
static __device__ __forceinline__ float gelu_exact(float x) {
    return 0.5f * x * (1.0f + erff(x * 0.70710678118654752f));
}
static __device__ __forceinline__ float red4(u64 a0, u64 a1) {
    float lo, hi; upk2(fadd2(a0, a1), lo, hi); return lo + hi;
}

#define FKJ(F00,F01,F02,F10,F11,F12,F20,F21,F22,PX,PY,PZ,TH) do {              \
    float s_, c_; __sincosf((TH), &s_, &c_);                                   \
    tx += r00*(PX) + r01*(PY) + r02*(PZ);                                      \
    ty += r10*(PX) + r11*(PY) + r12*(PZ);                                      \
    tz += r20*(PX) + r21*(PY) + r22*(PZ);                                      \
    float A0 = r00*(F00) + r01*(F10) + r02*(F20);                              \
    float A1 = r10*(F00) + r11*(F10) + r12*(F20);                              \
    float A2 = r20*(F00) + r21*(F10) + r22*(F20);                              \
    float B0 = r00*(F01) + r01*(F11) + r02*(F21);                              \
    float B1 = r10*(F01) + r11*(F11) + r12*(F21);                              \
    float B2 = r20*(F01) + r21*(F11) + r22*(F21);                              \
    float C0 = r00*(F02) + r01*(F12) + r02*(F22);                              \
    float C1 = r10*(F02) + r11*(F12) + r12*(F22);                              \
    float C2v = r20*(F02) + r21*(F12) + r22*(F22);                             \
    r00 = c_*A0 + s_*B0;  r01 = c_*B0 - s_*A0;  r02 = C0;                      \
    r10 = c_*A1 + s_*B1;  r11 = c_*B1 - s_*A1;  r12 = C1;                      \
    r20 = c_*A2 + s_*B2;  r21 = c_*B2 - s_*A2;  r22 = C2v;                     \
} while (0)

// FK + all_kp store + (projection & xp build | final outputs)
static __device__ __forceinline__ void front_sample(
    int s, int it, const float* th, float vm,
    const float* __restrict__ tgt2d, const float* __restrict__ camK,
    const float* __restrict__ Rext,  const float* __restrict__ text,
    float* __restrict__ outAllKp, float* __restrict__ outKp,
    float* __restrict__ outTheta, u64* xp, int last)
{
    float kx[7], ky[7], kz[7];
    float r00=1.f,r01=0.f,r02=0.f, r10=0.f,r11=1.f,r12=0.f, r20=0.f,r21=0.f,r22=1.f;
    float tx=0.f, ty=0.f, tz=0.f;
    FKJ(1,0,0,  0,1,0,  0,0,1,   0.f,      0.f,     0.333f, th[0]);
    FKJ(1,0,0,  0,0,1,  0,-1,0,  0.f,      0.f,     0.f,    th[1]);
    kx[1]=tx; ky[1]=ty; kz[1]=tz;
    FKJ(1,0,0,  0,0,-1, 0,1,0,   0.f,     -0.316f,  0.f,    th[2]);
    kx[2]=tx; ky[2]=ty; kz[2]=tz;
    FKJ(1,0,0,  0,0,-1, 0,1,0,   0.0825f,  0.f,     0.f,    th[3]);
    kx[3]=tx; ky[3]=ty; kz[3]=tz;
    FKJ(1,0,0,  0,0,1,  0,-1,0, -0.0825f,  0.384f,  0.f,    th[4]);
    FKJ(1,0,0,  0,0,-1, 0,1,0,   0.f,      0.f,     0.f,    th[5]);
    kx[4]=tx; ky[4]=ty; kz[4]=tz;
    FKJ(1,0,0,  0,0,-1, 0,1,0,   0.088f,   0.f,     0.f,    th[6]);
    kx[5]=tx; ky[5]=ty; kz[5]=tz;
    kx[6]=tx + 0.107f*r02; ky[6]=ty + 0.107f*r12; kz[6]=tz + 0.107f*r22;
    kx[0]=0.f; ky[0]=0.f; kz[0]=0.f;

    {
        float* p = outAllKp + ((size_t)it * B_TOT + s) * 21;
#pragma unroll
        for (int k = 0; k < 7; k++) { p[3*k]=kx[k]; p[3*k+1]=ky[k]; p[3*k+2]=kz[k]; }
    }
    if (last) {
#pragma unroll
        for (int jj = 0; jj < 7; jj++) outTheta[(size_t)s*7 + jj] = th[jj];
        float* pkf = outKp + (size_t)s*21;
#pragma unroll
        for (int k = 0; k < 7; k++) { pkf[3*k]=kx[k]; pkf[3*k+1]=ky[k]; pkf[3*k+2]=kz[k]; }
        return;
    }
    float re[9], Kc[9], te[3];
#pragma unroll
    for (int i = 0; i < 9; i++) { re[i] = Rext[(size_t)s*9+i]; Kc[i] = camK[(size_t)s*9+i]; }
#pragma unroll
    for (int i = 0; i < 3; i++) te[i] = text[(size_t)s*3+i];
    float dmag[7];
#pragma unroll
    for (int k = 0; k < 7; k++) {
        float cxm = re[0]*kx[k] + re[1]*ky[k] + re[2]*kz[k] + te[0];
        float cym = re[3]*kx[k] + re[4]*ky[k] + re[5]*kz[k] + te[1];
        float czm = re[6]*kx[k] + re[7]*ky[k] + re[8]*kz[k] + te[2];
        float iz = 1.0f / fmaxf(czm, 1e-6f);
        float nx = cxm*iz, ny = cym*iz, nz = czm*iz;
        float u = Kc[0]*nx + Kc[1]*ny + Kc[2]*nz;
        float v = Kc[3]*nx + Kc[4]*ny + Kc[5]*nz;
        float du = (tgt2d[(size_t)s*14 + 2*k    ] - u) * vm;
        float dv = (tgt2d[(size_t)s*14 + 2*k + 1] - v) * vm;
        xp[k] = pk2(du, dv);
        dmag[k] = sqrtf(du*du + dv*dv);
    }
    xp[7]  = pk2(th[0], th[1]);   xp[8]  = pk2(th[2], th[3]);
    xp[9]  = pk2(th[4], th[5]);   xp[10] = pk2(th[6], dmag[0]);
    xp[11] = pk2(dmag[1], dmag[2]); xp[12] = pk2(dmag[3], dmag[4]);
    xp[13] = pk2(dmag[5], dmag[6]);
}

__global__ __launch_bounds__(THREADS,1)
void irm_kernel(const float* __restrict__ ang0,  const float* __restrict__ tgt2d,
                const float* __restrict__ camK,  const float* __restrict__ Rext,
                const float* __restrict__ text,  const int* __restrict__ vmask,
                const float* __restrict__ W1,    const float* __restrict__ b1,
                const float* __restrict__ g1,    const float* __restrict__ be1,
                const float* __restrict__ W2,    const float* __restrict__ b2,
                const float* __restrict__ g2,    const float* __restrict__ be2,
                const float* __restrict__ W3,    const float* __restrict__ b3,
                const float* __restrict__ slog,  float* __restrict__ out)
{
    extern __shared__ float smf[];
    char* const smc = (char*)smf;
    const int tid = threadIdx.x;

    // ================= per-CTA weight preprocessing (proven in R2) =================
    for (int idx = tid; idx < 1792; idx += THREADS) {
        int j = idx & 127, p = idx >> 7;
        smf[OFF_W1P + j*28 + p*2]     = W1[(2*p)  *128 + j];
        smf[OFF_W1P + j*28 + p*2 + 1] = W1[(2*p+1)*128 + j];
    }
    if (tid < 128) smf[OFF_B1 + tid] = b1[tid];
    for (int idx = tid; idx < 8192; idx += THREADS) {
        int j = idx & 127, p = idx >> 7;
        smf[OFF_W2G + j*128 + p*2]     = g1[2*p]   * W2[(2*p)  *128 + j];
        smf[OFF_W2G + j*128 + p*2 + 1] = g1[2*p+1] * W2[(2*p+1)*128 + j];
    }
    if (tid < 128) {
        float ga = 0.f, ca = 0.f;
        for (int k = 0; k < 128; k++) { float w = W2[k*128 + tid]; ga += g1[k]*w; ca += be1[k]*w; }
        ((float2*)(smf + OFF_G2C2))[tid] = make_float2(ga, ca + b2[tid]);
    }
    for (int idx = tid; idx < 512; idx += THREADS) {
        int k = idx & 127, p = idx >> 7;
        float gk = g2[k];
        int j0 = 2*p, j1 = 2*p + 1;
        smf[OFF_W3G + k*8 + p*2]     = gk * W3[k*7 + j0];
        smf[OFF_W3G + k*8 + p*2 + 1] = (j1 < 7) ? gk * W3[k*7 + j1] : 0.0f;
    }
    if (tid < 8) {
        float ga = 0.f, ca = 0.f;
        if (tid < 7) {
            for (int k = 0; k < 128; k++) { float w = W3[k*7 + tid]; ga += g2[k]*w; ca += be2[k]*w; }
            ca += b3[tid];
        }
        smf[OFF_G3 + tid] = ga;  smf[OFF_C3 + tid] = ca;
    }
    __syncthreads();

    // ================= per-thread: 2 samples =================
    const int sA = blockIdx.x * (THREADS*SPT) + tid;
    const int sB = sA + THREADS;
    float thA[7], thB[7];
#pragma unroll
    for (int j = 0; j < 7; j++) { thA[j] = ang0[sA*7 + j]; thB[j] = ang0[sB*7 + j]; }
    const float vmA = (vmask[sA] != 0) ? 1.0f : 0.0f;
    const float vmB = (vmask[sB] != 0) ? 1.0f : 0.0f;

    float* const outTheta = out;
    float* const outKp    = out + (size_t)B_TOT*7;
    float* const outAng   = out + (size_t)B_TOT*28;
    float* const outAllKp = out + (size_t)B_TOT*56;
#pragma unroll
    for (int j = 0; j < 7; j++) { outAng[(size_t)sA*7 + j] = thA[j]; outAng[(size_t)sB*7 + j] = thB[j]; }

    char* const h1me = smc + H1_BYTE + tid*16;   // chunk c at + c*4096; chunk = 4 floats = 2 pairs

    for (int it = 0; it < 4; ++it) {
        u64 xpA[14], xpB[14];
        const int last = (it == 3);
        front_sample(sA, it, thA, vmA, tgt2d, camK, Rext, text, outAllKp, outKp, outTheta, xpA, last);
        front_sample(sB, it, thB, vmB, tgt2d, camK, Rext, text, outAllKp, outKp, outTheta, xpB, last);
        if (last) break;

        // ---------------- layer 1 (shared W1 stream, 2 samples) ----------------
        // A's h1 -> registers (u64 pairs, exact fp32); B's h1 -> SMEM fp32 pairs.
        u64 h1A[64];
        float sumA=0.f, sqA=0.f, sumB=0.f, sqB=0.f;
        for (int j2o = 0; j2o < 16; j2o++) {
            u64 pB[4];
#pragma unroll
            for (int u = 0; u < 4; u++) {
                const int j2 = 4*j2o + u;
                const ulonglong2* wa = (const ulonglong2*)(smf + OFF_W1P + (2*j2)  *28);
                const ulonglong2* wb = (const ulonglong2*)(smf + OFF_W1P + (2*j2+1)*28);
                u64 aA0=0,aA1=0,cA0=0,cA1=0, aB0=0,aB1=0,cB0=0,cB1=0;
#pragma unroll
                for (int q = 0; q < 7; q++) {
                    ulonglong2 va = wa[q], vb = wb[q];
                    aA0 = ffma2(xpA[2*q],   va.x, aA0);
                    aA1 = ffma2(xpA[2*q+1], va.y, aA1);
                    cA0 = ffma2(xpA[2*q],   vb.x, cA0);
                    cA1 = ffma2(xpA[2*q+1], vb.y, cA1);
                    aB0 = ffma2(xpB[2*q],   va.x, aB0);
                    aB1 = ffma2(xpB[2*q+1], va.y, aB1);
                    cB0 = ffma2(xpB[2*q],   vb.x, cB0);
                    cB1 = ffma2(xpB[2*q+1], vb.y, cB1);
                }
                float bb0 = smf[OFF_B1 + 2*j2], bb1 = smf[OFF_B1 + 2*j2 + 1];
                float v0A = gelu_exact(red4(aA0,aA1) + bb0);
                float v1A = gelu_exact(red4(cA0,cA1) + bb1);
                float v0B = gelu_exact(red4(aB0,aB1) + bb0);
                float v1B = gelu_exact(red4(cB0,cB1) + bb1);
                sumA += v0A + v1A;  sqA += v0A*v0A + v1A*v1A;
                sumB += v0B + v1B;  sqB += v0B*v0B + v1B*v1B;
                h1A[j2o*4 + u] = pk2(v0A, v1A);
                pB[u] = pk2(v0B, v1B);
            }
            *(ulonglong2*)(h1me + (2*j2o)  *4096) = make_ulonglong2(pB[0], pB[1]);
            *(ulonglong2*)(h1me + (2*j2o+1)*4096) = make_ulonglong2(pB[2], pB[3]);
        }
        float muA = sumA*(1.0f/128.0f);
        float rsA = rsqrtf(sqA*(1.0f/128.0f) - muA*muA + 1e-5f);
        float bcoA = rsA*muA;
        float muB = sumB*(1.0f/128.0f);
        float rsB = rsqrtf(sqB*(1.0f/128.0f) - muB*muB + 1e-5f);
        float bcoB = rsB*muB;

        // ---------------- layer 2 + 3 (shared W2/W3 streams) ----------------
        float sum2A=0.f, sq2A=0.f, sum2B=0.f, sq2B=0.f;
        u64 SA0=0,SA1=0,SA2=0,SA3=0, SB0=0,SB1=0,SB2=0,SB3=0;
        const float2* const G2C2 = (const float2*)(smf + OFF_G2C2);

        for (int jt = 0; jt < 8; jt++) {
            float accA[16], accB[16];
#pragma unroll
            for (int j = 0; j < 16; j++) { accA[j] = 0.f; accB[j] = 0.f; }
            for (int kh = 0; kh < 4; kh++) {
                u64 hB[16];
#pragma unroll
                for (int cc = 0; cc < 8; cc++) {
                    ulonglong2 rb = *(const ulonglong2*)(h1me + (kh*8+cc)*4096);
                    hB[cc*2]   = rb.x;
                    hB[cc*2+1] = rb.y;
                }
#pragma unroll
                for (int j = 0; j < 16; j++) {
                    const int row = jt*16 + j;
                    const ulonglong2* wr = (const ulonglong2*)(smf + OFF_W2G + row*128 + kh*32);
                    u64 a0=0,a1=0, b0=0,b1=0;
#pragma unroll
                    for (int q = 0; q < 8; q++) {
                        ulonglong2 w = wr[q];
                        a0 = ffma2(h1A[kh*16 + 2*q],   w.x, a0);
                        a1 = ffma2(h1A[kh*16 + 2*q+1], w.y, a1);
                        b0 = ffma2(hB[2*q],   w.x, b0);
                        b1 = ffma2(hB[2*q+1], w.y, b1);
                    }
                    accA[j] += red4(a0,a1);
                    accB[j] += red4(b0,b1);
                }
            }
            // finalize this j-block: LN1-fold -> GELU -> stats + layer3 accum
#pragma unroll
            for (int j = 0; j < 16; j++) {
                const int row = jt*16 + j;
                float2 gc = G2C2[row];
                float vA = gelu_exact(rsA*accA[j] - bcoA*gc.x + gc.y);
                float vB = gelu_exact(rsB*accB[j] - bcoB*gc.x + gc.y);
                sum2A += vA; sq2A += vA*vA;
                sum2B += vB; sq2B += vB*vB;
                const ulonglong2* w3r = (const ulonglong2*)(smf + OFF_W3G + row*8);
                ulonglong2 wa3 = w3r[0], wb3 = w3r[1];
                u64 vA2 = pk2(vA,vA), vB2 = pk2(vB,vB);
                SA0 = ffma2(vA2, wa3.x, SA0);  SA1 = ffma2(vA2, wa3.y, SA1);
                SA2 = ffma2(vA2, wb3.x, SA2);  SA3 = ffma2(vA2, wb3.y, SA3);
                SB0 = ffma2(vB2, wa3.x, SB0);  SB1 = ffma2(vB2, wa3.y, SB1);
                SB2 = ffma2(vB2, wb3.x, SB2);  SB3 = ffma2(vB2, wb3.y, SB3);
            }
        }

        // ---------------- LN2 fold -> theta update ----------------
        float mu2A = sum2A*(1.0f/128.0f);
        float rs2A = rsqrtf(sq2A*(1.0f/128.0f) - mu2A*mu2A + 1e-5f);
        float bco2A = rs2A*mu2A;
        float mu2B = sum2B*(1.0f/128.0f);
        float rs2B = rsqrtf(sq2B*(1.0f/128.0f) - mu2B*mu2B + 1e-5f);
        float bco2B = rs2B*mu2B;
        float svA[8], svB[8];
        upk2(SA0, svA[0], svA[1]); upk2(SA1, svA[2], svA[3]);
        upk2(SA2, svA[4], svA[5]); upk2(SA3, svA[6], svA[7]);
        upk2(SB0, svB[0], svB[1]); upk2(SB1, svB[2], svB[3]);
        upk2(SB2, svB[4], svB[5]); upk2(SB3, svB[6], svB[7]);

        const float ssi = 1.0f/(1.0f + expf(-slog[it]));
        const float LO[7] = {-2.8973f,-1.7628f,-2.8973f,-3.0718f,-2.8973f,-0.0175f,-2.8973f};
        const float HI[7] = { 2.8973f, 1.7628f, 2.8973f,-0.0698f, 2.8973f, 3.7525f, 2.8973f};
#pragma unroll
        for (int jj = 0; jj < 7; jj++) {
            float dlA = rs2A*svA[jj] - bco2A*smf[OFF_G3 + jj] + smf[OFF_C3 + jj];
            float dlB = rs2B*svB[jj] - bco2B*smf[OFF_G3 + jj] + smf[OFF_C3 + jj];
            thA[jj] = fminf(fmaxf(thA[jj] + ssi*dlA, LO[jj]), HI[jj]);
            thB[jj] = fminf(fmaxf(thB[jj] + ssi*dlB, LO[jj]), HI[jj]);
        }
        float* paA = outAng + ((size_t)(it+1)*B_TOT + sA)*7;
        float* paB = outAng + ((size_t)(it+1)*B_TOT + sB)*7;
#pragma unroll
        for (int jj = 0; jj < 7; jj++) { paA[jj] = thA[jj]; paB[jj] = thB[jj]; }
    }
}

extern "C" void kernel_launch(void* const* d_in, const int* in_sizes, int n_in,
                              void* d_out, int out_size) {
    (void)in_sizes; (void)n_in; (void)out_size;
    cudaFuncSetAttribute(irm_kernel, cudaFuncAttributeMaxDynamicSharedMemorySize, SMEM_BYTES);
    irm_kernel<<<CTAS, THREADS, SMEM_BYTES>>>(
        (const float*)d_in[0], (const float*)d_in[1], (const float*)d_in[2],
        (const float*)d_in[4], (const float*)d_in[5], (const int*)d_in[6],
        (const float*)d_in[7],  (const float*)d_in[8],
        (const float*)d_in[9],  (const float*)d_in[10],
        (const float*)d_in[11], (const float*)d_in[12],
        (const float*)d_in[13], (const float*)d_in[14],
        (const float*)d_in[15], (const float*)d_in[16],
        (const float*)d_in[17],
        (float*)d_out);
}

// round 10
// speedup vs baseline: 1.1169x; 1.1169x over previous
#include <cuda_runtime.h>
#include <math.h>
#include <stdint.h>

#define B_TOT   262144
#define THREADS 256
#define SPT     2
#define CTAS    (B_TOT/(THREADS*SPT))   // 512

// ---- shared memory layout (float offsets; H1 in bytes) ----
#define OFF_W1P   0        // 128 rows x 14 pairs (28 floats) = 3584
#define OFF_B1    3584     // 128
#define OFF_W2G   3712     // 128 rows x 128 floats (g1-folded) = 16384
#define OFF_G2C2  20096    // float2[128] = 256 floats
#define OFF_W3G   20352    // 128 rows x 8 floats (g2-folded) = 1024
#define OFF_G3    21376    // 8
#define OFF_C3    21384    // 8
#define H1_BYTE   85568    // 32 chunks x 256 threads x 16B = 131072 B (B-sample h1, fp32)
#define SMEM_BYTES (H1_BYTE + 131072)   // 216640

typedef unsigned long long u64;

static __device__ __forceinline__ u64 pk2(float lo, float hi) {
    u64 r; asm("mov.b64 %0,{%1,%2};" : "=l"(r) : "f"(lo), "f"(hi)); return r;
}
static __device__ __forceinline__ void upk2(u64 v, float &lo, float &hi) {
    asm("mov.b64 {%0,%1},%2;" : "=f"(lo), "=f"(hi) : "l"(v));
}
static __device__ __forceinline__ u64 ffma2(u64 a, u64 b, u64 c) {
    u64 d; asm("fma.rn.f32x2 %0,%1,%2,%3;" : "=l"(d) : "l"(a), "l"(b), "l"(c)); return d;
}
static __device__ __forceinline__ u64 fadd2(u64 a, u64 b) {
    u64 d; asm("add.rn.f32x2 %0,%1,%2;" : "=l"(d) : "l"(a), "l"(b)); return d;
}
static __device__ __forceinline__ float gelu_exact(float x) {
    return 0.5f * x * (1.0f + erff(x * 0.70710678118654752f));
}
static __device__ __forceinline__ float red4(u64 a0, u64 a1) {
    float lo, hi; upk2(fadd2(a0, a1), lo, hi); return lo + hi;
}

#define FKJ(F00,F01,F02,F10,F11,F12,F20,F21,F22,PX,PY,PZ,TH) do {              \
    float s_, c_; __sincosf((TH), &s_, &c_);                                   \
    tx += r00*(PX) + r01*(PY) + r02*(PZ);                                      \
    ty += r10*(PX) + r11*(PY) + r12*(PZ);                                      \
    tz += r20*(PX) + r21*(PY) + r22*(PZ);                                      \
    float A0 = r00*(F00) + r01*(F10) + r02*(F20);                              \
    float A1 = r10*(F00) + r11*(F10) + r12*(F20);                              \
    float A2 = r20*(F00) + r21*(F10) + r22*(F20);                              \
    float B0 = r00*(F01) + r01*(F11) + r02*(F21);                              \
    float B1 = r10*(F01) + r11*(F11) + r12*(F21);                              \
    float B2 = r20*(F01) + r21*(F11) + r22*(F21);                              \
    float C0 = r00*(F02) + r01*(F12) + r02*(F22);                              \
    float C1 = r10*(F02) + r11*(F12) + r12*(F22);                              \
    float C2v = r20*(F02) + r21*(F12) + r22*(F22);                             \
    r00 = c_*A0 + s_*B0;  r01 = c_*B0 - s_*A0;  r02 = C0;                      \
    r10 = c_*A1 + s_*B1;  r11 = c_*B1 - s_*A1;  r12 = C1;                      \
    r20 = c_*A2 + s_*B2;  r21 = c_*B2 - s_*A2;  r22 = C2v;                     \
} while (0)

// FK + all_kp store + (projection & xp build | final outputs)
static __device__ __forceinline__ void front_sample(
    int s, int it, const float* th, float vm,
    const float* __restrict__ tgt2d, const float* __restrict__ camK,
    const float* __restrict__ Rext,  const float* __restrict__ text,
    float* __restrict__ outAllKp, float* __restrict__ outKp,
    float* __restrict__ outTheta, u64* xp, int last)
{
    float kx[7], ky[7], kz[7];
    float r00=1.f,r01=0.f,r02=0.f, r10=0.f,r11=1.f,r12=0.f, r20=0.f,r21=0.f,r22=1.f;
    float tx=0.f, ty=0.f, tz=0.f;
    FKJ(1,0,0,  0,1,0,  0,0,1,   0.f,      0.f,     0.333f, th[0]);
    FKJ(1,0,0,  0,0,1,  0,-1,0,  0.f,      0.f,     0.f,    th[1]);
    kx[1]=tx; ky[1]=ty; kz[1]=tz;
    FKJ(1,0,0,  0,0,-1, 0,1,0,   0.f,     -0.316f,  0.f,    th[2]);
    kx[2]=tx; ky[2]=ty; kz[2]=tz;
    FKJ(1,0,0,  0,0,-1, 0,1,0,   0.0825f,  0.f,     0.f,    th[3]);
    kx[3]=tx; ky[3]=ty; kz[3]=tz;
    FKJ(1,0,0,  0,0,1,  0,-1,0, -0.0825f,  0.384f,  0.f,    th[4]);
    FKJ(1,0,0,  0,0,-1, 0,1,0,   0.f,      0.f,     0.f,    th[5]);
    kx[4]=tx; ky[4]=ty; kz[4]=tz;
    FKJ(1,0,0,  0,0,-1, 0,1,0,   0.088f,   0.f,     0.f,    th[6]);
    kx[5]=tx; ky[5]=ty; kz[5]=tz;
    kx[6]=tx + 0.107f*r02; ky[6]=ty + 0.107f*r12; kz[6]=tz + 0.107f*r22;
    kx[0]=0.f; ky[0]=0.f; kz[0]=0.f;

    {
        float* p = outAllKp + ((size_t)it * B_TOT + s) * 21;
#pragma unroll
        for (int k = 0; k < 7; k++) { p[3*k]=kx[k]; p[3*k+1]=ky[k]; p[3*k+2]=kz[k]; }
    }
    if (last) {
#pragma unroll
        for (int jj = 0; jj < 7; jj++) outTheta[(size_t)s*7 + jj] = th[jj];
        float* pkf = outKp + (size_t)s*21;
#pragma unroll
        for (int k = 0; k < 7; k++) { pkf[3*k]=kx[k]; pkf[3*k+1]=ky[k]; pkf[3*k+2]=kz[k]; }
        return;
    }
    float re[9], Kc[9], te[3];
#pragma unroll
    for (int i = 0; i < 9; i++) { re[i] = Rext[(size_t)s*9+i]; Kc[i] = camK[(size_t)s*9+i]; }
#pragma unroll
    for (int i = 0; i < 3; i++) te[i] = text[(size_t)s*3+i];
    float dmag[7];
#pragma unroll
    for (int k = 0; k < 7; k++) {
        float cxm = re[0]*kx[k] + re[1]*ky[k] + re[2]*kz[k] + te[0];
        float cym = re[3]*kx[k] + re[4]*ky[k] + re[5]*kz[k] + te[1];
        float czm = re[6]*kx[k] + re[7]*ky[k] + re[8]*kz[k] + te[2];
        float iz = 1.0f / fmaxf(czm, 1e-6f);
        float nx = cxm*iz, ny = cym*iz, nz = czm*iz;
        float u = Kc[0]*nx + Kc[1]*ny + Kc[2]*nz;
        float v = Kc[3]*nx + Kc[4]*ny + Kc[5]*nz;
        float du = (tgt2d[(size_t)s*14 + 2*k    ] - u) * vm;
        float dv = (tgt2d[(size_t)s*14 + 2*k + 1] - v) * vm;
        xp[k] = pk2(du, dv);
        dmag[k] = sqrtf(du*du + dv*dv);
    }
    xp[7]  = pk2(th[0], th[1]);   xp[8]  = pk2(th[2], th[3]);
    xp[9]  = pk2(th[4], th[5]);   xp[10] = pk2(th[6], dmag[0]);
    xp[11] = pk2(dmag[1], dmag[2]); xp[12] = pk2(dmag[3], dmag[4]);
    xp[13] = pk2(dmag[5], dmag[6]);
}

__global__ __launch_bounds__(THREADS,1)
void irm_kernel(const float* __restrict__ ang0,  const float* __restrict__ tgt2d,
                const float* __restrict__ camK,  const float* __restrict__ Rext,
                const float* __restrict__ text,  const int* __restrict__ vmask,
                const float* __restrict__ W1,    const float* __restrict__ b1,
                const float* __restrict__ g1,    const float* __restrict__ be1,
                const float* __restrict__ W2,    const float* __restrict__ b2,
                const float* __restrict__ g2,    const float* __restrict__ be2,
                const float* __restrict__ W3,    const float* __restrict__ b3,
                const float* __restrict__ slog,  float* __restrict__ out)
{
    extern __shared__ float smf[];
    char* const smc = (char*)smf;
    const int tid = threadIdx.x;

    // ================= per-CTA weight preprocessing (proven in R2) =================
    for (int idx = tid; idx < 1792; idx += THREADS) {
        int j = idx & 127, p = idx >> 7;
        smf[OFF_W1P + j*28 + p*2]     = W1[(2*p)  *128 + j];
        smf[OFF_W1P + j*28 + p*2 + 1] = W1[(2*p+1)*128 + j];
    }
    if (tid < 128) smf[OFF_B1 + tid] = b1[tid];
    for (int idx = tid; idx < 8192; idx += THREADS) {
        int j = idx & 127, p = idx >> 7;
        smf[OFF_W2G + j*128 + p*2]     = g1[2*p]   * W2[(2*p)  *128 + j];
        smf[OFF_W2G + j*128 + p*2 + 1] = g1[2*p+1] * W2[(2*p+1)*128 + j];
    }
    if (tid < 128) {
        float ga = 0.f, ca = 0.f;
        for (int k = 0; k < 128; k++) { float w = W2[k*128 + tid]; ga += g1[k]*w; ca += be1[k]*w; }
        ((float2*)(smf + OFF_G2C2))[tid] = make_float2(ga, ca + b2[tid]);
    }
    for (int idx = tid; idx < 512; idx += THREADS) {
        int k = idx & 127, p = idx >> 7;
        float gk = g2[k];
        int j0 = 2*p, j1 = 2*p + 1;
        smf[OFF_W3G + k*8 + p*2]     = gk * W3[k*7 + j0];
        smf[OFF_W3G + k*8 + p*2 + 1] = (j1 < 7) ? gk * W3[k*7 + j1] : 0.0f;
    }
    if (tid < 8) {
        float ga = 0.f, ca = 0.f;
        if (tid < 7) {
            for (int k = 0; k < 128; k++) { float w = W3[k*7 + tid]; ga += g2[k]*w; ca += be2[k]*w; }
            ca += b3[tid];
        }
        smf[OFF_G3 + tid] = ga;  smf[OFF_C3 + tid] = ca;
    }
    __syncthreads();

    // ================= per-thread: 2 samples =================
    const int sA = blockIdx.x * (THREADS*SPT) + tid;
    const int sB = sA + THREADS;
    float thA[7], thB[7];
#pragma unroll
    for (int j = 0; j < 7; j++) { thA[j] = ang0[sA*7 + j]; thB[j] = ang0[sB*7 + j]; }
    const float vmA = (vmask[sA] != 0) ? 1.0f : 0.0f;
    const float vmB = (vmask[sB] != 0) ? 1.0f : 0.0f;

    float* const outTheta = out;
    float* const outKp    = out + (size_t)B_TOT*7;
    float* const outAng   = out + (size_t)B_TOT*28;
    float* const outAllKp = out + (size_t)B_TOT*56;
#pragma unroll
    for (int j = 0; j < 7; j++) { outAng[(size_t)sA*7 + j] = thA[j]; outAng[(size_t)sB*7 + j] = thB[j]; }

    char* const h1me = smc + H1_BYTE + tid*16;   // chunk c at + c*4096; chunk = 4 floats = 2 pairs

    for (int it = 0; it < 4; ++it) {
        u64 xpA[14], xpB[14];
        const int last = (it == 3);
        front_sample(sA, it, thA, vmA, tgt2d, camK, Rext, text, outAllKp, outKp, outTheta, xpA, last);
        front_sample(sB, it, thB, vmB, tgt2d, camK, Rext, text, outAllKp, outKp, outTheta, xpB, last);
        if (last) break;

        // ---------------- layer 1 (shared W1 stream, 2 samples) ----------------
        // A's h1 -> registers (u64 pairs, exact fp32); B's h1 -> SMEM fp32 pairs.
        u64 h1A[64];
        float sumA=0.f, sqA=0.f, sumB=0.f, sqB=0.f;
        for (int j2o = 0; j2o < 16; j2o++) {
            u64 pB[4];
#pragma unroll
            for (int u = 0; u < 4; u++) {
                const int j2 = 4*j2o + u;
                const ulonglong2* wa = (const ulonglong2*)(smf + OFF_W1P + (2*j2)  *28);
                const ulonglong2* wb = (const ulonglong2*)(smf + OFF_W1P + (2*j2+1)*28);
                u64 aA0=0,aA1=0,cA0=0,cA1=0, aB0=0,aB1=0,cB0=0,cB1=0;
#pragma unroll
                for (int q = 0; q < 7; q++) {
                    ulonglong2 va = wa[q], vb = wb[q];
                    aA0 = ffma2(xpA[2*q],   va.x, aA0);
                    aA1 = ffma2(xpA[2*q+1], va.y, aA1);
                    cA0 = ffma2(xpA[2*q],   vb.x, cA0);
                    cA1 = ffma2(xpA[2*q+1], vb.y, cA1);
                    aB0 = ffma2(xpB[2*q],   va.x, aB0);
                    aB1 = ffma2(xpB[2*q+1], va.y, aB1);
                    cB0 = ffma2(xpB[2*q],   vb.x, cB0);
                    cB1 = ffma2(xpB[2*q+1], vb.y, cB1);
                }
                float bb0 = smf[OFF_B1 + 2*j2], bb1 = smf[OFF_B1 + 2*j2 + 1];
                float v0A = gelu_exact(red4(aA0,aA1) + bb0);
                float v1A = gelu_exact(red4(cA0,cA1) + bb1);
                float v0B = gelu_exact(red4(aB0,aB1) + bb0);
                float v1B = gelu_exact(red4(cB0,cB1) + bb1);
                sumA += v0A + v1A;  sqA += v0A*v0A + v1A*v1A;
                sumB += v0B + v1B;  sqB += v0B*v0B + v1B*v1B;
                h1A[j2o*4 + u] = pk2(v0A, v1A);
                pB[u] = pk2(v0B, v1B);
            }
            *(ulonglong2*)(h1me + (2*j2o)  *4096) = make_ulonglong2(pB[0], pB[1]);
            *(ulonglong2*)(h1me + (2*j2o+1)*4096) = make_ulonglong2(pB[2], pB[3]);
        }
        float muA = sumA*(1.0f/128.0f);
        float rsA = rsqrtf(sqA*(1.0f/128.0f) - muA*muA + 1e-5f);
        float bcoA = rsA*muA;
        float muB = sumB*(1.0f/128.0f);
        float rsB = rsqrtf(sqB*(1.0f/128.0f) - muB*muB + 1e-5f);
        float bcoB = rsB*muB;

        // ---------------- layer 2 + 3 (shared W2/W3 streams, j-tile 8) ----------------
        float sum2A=0.f, sq2A=0.f, sum2B=0.f, sq2B=0.f;
        u64 SA0=0,SA1=0,SA2=0,SA3=0, SB0=0,SB1=0,SB2=0,SB3=0;
        const float2* const G2C2 = (const float2*)(smf + OFF_G2C2);

        for (int jt = 0; jt < 16; jt++) {
            float accA[8], accB[8];
#pragma unroll
            for (int j = 0; j < 8; j++) { accA[j] = 0.f; accB[j] = 0.f; }
            for (int kh = 0; kh < 4; kh++) {
                u64 hB[16];
#pragma unroll
                for (int cc = 0; cc < 8; cc++) {
                    ulonglong2 rb = *(const ulonglong2*)(h1me + (kh*8+cc)*4096);
                    hB[cc*2]   = rb.x;
                    hB[cc*2+1] = rb.y;
                }
#pragma unroll
                for (int j = 0; j < 8; j++) {
                    const int row = jt*8 + j;
                    const ulonglong2* wr = (const ulonglong2*)(smf + OFF_W2G + row*128 + kh*32);
                    u64 a0=0,a1=0, b0=0,b1=0;
#pragma unroll
                    for (int q = 0; q < 8; q++) {
                        ulonglong2 w = wr[q];
                        a0 = ffma2(h1A[kh*16 + 2*q],   w.x, a0);
                        a1 = ffma2(h1A[kh*16 + 2*q+1], w.y, a1);
                        b0 = ffma2(hB[2*q],   w.x, b0);
                        b1 = ffma2(hB[2*q+1], w.y, b1);
                    }
                    accA[j] += red4(a0,a1);
                    accB[j] += red4(b0,b1);
                }
            }
            // finalize this j-block: LN1-fold -> GELU -> stats + layer3 accum
#pragma unroll
            for (int j = 0; j < 8; j++) {
                const int row = jt*8 + j;
                float2 gc = G2C2[row];
                float vA = gelu_exact(rsA*accA[j] - bcoA*gc.x + gc.y);
                float vB = gelu_exact(rsB*accB[j] - bcoB*gc.x + gc.y);
                sum2A += vA; sq2A += vA*vA;
                sum2B += vB; sq2B += vB*vB;
                const ulonglong2* w3r = (const ulonglong2*)(smf + OFF_W3G + row*8);
                ulonglong2 wa3 = w3r[0], wb3 = w3r[1];
                u64 vA2 = pk2(vA,vA), vB2 = pk2(vB,vB);
                SA0 = ffma2(vA2, wa3.x, SA0);  SA1 = ffma2(vA2, wa3.y, SA1);
                SA2 = ffma2(vA2, wb3.x, SA2);  SA3 = ffma2(vA2, wb3.y, SA3);
                SB0 = ffma2(vB2, wa3.x, SB0);  SB1 = ffma2(vB2, wa3.y, SB1);
                SB2 = ffma2(vB2, wb3.x, SB2);  SB3 = ffma2(vB2, wb3.y, SB3);
            }
        }

        // ---------------- LN2 fold -> theta update ----------------
        float mu2A = sum2A*(1.0f/128.0f);
        float rs2A = rsqrtf(sq2A*(1.0f/128.0f) - mu2A*mu2A + 1e-5f);
        float bco2A = rs2A*mu2A;
        float mu2B = sum2B*(1.0f/128.0f);
        float rs2B = rsqrtf(sq2B*(1.0f/128.0f) - mu2B*mu2B + 1e-5f);
        float bco2B = rs2B*mu2B;
        float svA[8], svB[8];
        upk2(SA0, svA[0], svA[1]); upk2(SA1, svA[2], svA[3]);
        upk2(SA2, svA[4], svA[5]); upk2(SA3, svA[6], svA[7]);
        upk2(SB0, svB[0], svB[1]); upk2(SB1, svB[2], svB[3]);
        upk2(SB2, svB[4], svB[5]); upk2(SB3, svB[6], svB[7]);

        const float ssi = 1.0f/(1.0f + expf(-slog[it]));
        const float LO[7] = {-2.8973f,-1.7628f,-2.8973f,-3.0718f,-2.8973f,-0.0175f,-2.8973f};
        const float HI[7] = { 2.8973f, 1.7628f, 2.8973f,-0.0698f, 2.8973f, 3.7525f, 2.8973f};
#pragma unroll
        for (int jj = 0; jj < 7; jj++) {
            float dlA = rs2A*svA[jj] - bco2A*smf[OFF_G3 + jj] + smf[OFF_C3 + jj];
            float dlB = rs2B*svB[jj] - bco2B*smf[OFF_G3 + jj] + smf[OFF_C3 + jj];
            thA[jj] = fminf(fmaxf(thA[jj] + ssi*dlA, LO[jj]), HI[jj]);
            thB[jj] = fminf(fmaxf(thB[jj] + ssi*dlB, LO[jj]), HI[jj]);
        }
        float* paA = outAng + ((size_t)(it+1)*B_TOT + sA)*7;
        float* paB = outAng + ((size_t)(it+1)*B_TOT + sB)*7;
#pragma unroll
        for (int jj = 0; jj < 7; jj++) { paA[jj] = thA[jj]; paB[jj] = thB[jj]; }
    }
}

extern "C" void kernel_launch(void* const* d_in, const int* in_sizes, int n_in,
                              void* d_out, int out_size) {
    (void)in_sizes; (void)n_in; (void)out_size;
    cudaFuncSetAttribute(irm_kernel, cudaFuncAttributeMaxDynamicSharedMemorySize, SMEM_BYTES);
    irm_kernel<<<CTAS, THREADS, SMEM_BYTES>>>(
        (const float*)d_in[0], (const float*)d_in[1], (const float*)d_in[2],
        (const float*)d_in[4], (const float*)d_in[5], (const int*)d_in[6],
        (const float*)d_in[7],  (const float*)d_in[8],
        (const float*)d_in[9],  (const float*)d_in[10],
        (const float*)d_in[11], (const float*)d_in[12],
        (const float*)d_in[13], (const float*)d_in[14],
        (const float*)d_in[15], (const float*)d_in[16],
        (const float*)d_in[17],
        (float*)d_out);
}

// round 11
// speedup vs baseline: 1.8046x; 1.6157x over previous
#include <cuda_runtime.h>
#include <cuda_bf16.h>
#include <math.h>
#include <stdint.h>

#define B_TOT   262144
#define THREADS 256
#define CTAS    (B_TOT/THREADS)   // 1024

// ---- SMEM layout (bytes) ----
#define W1P_O   0        // 3584 floats (pairs layout) = 14336
#define B1_O    14336    // 128 f
#define G2C2_O  14848    // float2[128]
#define W3G_O   15872    // 128*8 f
#define G3_O    19968    // 8 f
#define C3_O    20000    // 8 f
#define W2H_O   20032    // 128 rows x 272 B bf16 (g1-folded hi)
#define W2L_O   54848    // lo
#define H1H_O   89664    // 256 rows x 272 B bf16 (h1 hi)
#define H1L_O   159296   // h1 lo
#define SMEM_BYTES 228928
#define H2_O    H1H_O    // overlay: 32 chunks x 4096 B (f32 [chunk][sample][4])

typedef unsigned long long u64;

static __device__ __forceinline__ u64 pk2(float lo, float hi) {
    u64 r; asm("mov.b64 %0,{%1,%2};" : "=l"(r) : "f"(lo), "f"(hi)); return r;
}
static __device__ __forceinline__ void upk2(u64 v, float &lo, float &hi) {
    asm("mov.b64 {%0,%1},%2;" : "=f"(lo), "=f"(hi) : "l"(v));
}
static __device__ __forceinline__ u64 ffma2(u64 a, u64 b, u64 c) {
    u64 d; asm("fma.rn.f32x2 %0,%1,%2,%3;" : "=l"(d) : "l"(a), "l"(b), "l"(c)); return d;
}
static __device__ __forceinline__ u64 fadd2(u64 a, u64 b) {
    u64 d; asm("add.rn.f32x2 %0,%1,%2;" : "=l"(d) : "l"(a), "l"(b)); return d;
}
static __device__ __forceinline__ float gelu_exact(float x) {
    return 0.5f * x * (1.0f + erff(x * 0.70710678118654752f));
}
static __device__ __forceinline__ float red4(u64 a0, u64 a1) {
    float lo, hi; upk2(fadd2(a0, a1), lo, hi); return lo + hi;
}
static __device__ __forceinline__ uint32_t s2u(const void* p){
    uint32_t a; asm("{ .reg .u64 t; cvta.to.shared.u64 t, %1; cvt.u32.u64 %0, t; }":"=r"(a):"l"(p)); return a;
}
static __device__ __forceinline__ void ldsm4(uint32_t& r0,uint32_t& r1,uint32_t& r2,uint32_t& r3, uint32_t a){
    asm volatile("ldmatrix.sync.aligned.m8n8.x4.shared.b16 {%0,%1,%2,%3}, [%4];"
        : "=r"(r0),"=r"(r1),"=r"(r2),"=r"(r3) : "r"(a));
}
static __device__ __forceinline__ void ldsm4t(uint32_t& r0,uint32_t& r1,uint32_t& r2,uint32_t& r3, uint32_t a){
    asm volatile("ldmatrix.sync.aligned.m8n8.x4.trans.shared.b16 {%0,%1,%2,%3}, [%4];"
        : "=r"(r0),"=r"(r1),"=r"(r2),"=r"(r3) : "r"(a));
}
static __device__ __forceinline__ void mma16816(float* d, const uint32_t* a, uint32_t b0, uint32_t b1){
    asm volatile("mma.sync.aligned.m16n8k16.row.col.f32.bf16.bf16.f32 "
        "{%0,%1,%2,%3}, {%4,%5,%6,%7}, {%8,%9}, {%0,%1,%2,%3};"
        : "+f"(d[0]),"+f"(d[1]),"+f"(d[2]),"+f"(d[3])
        : "r"(a[0]),"r"(a[1]),"r"(a[2]),"r"(a[3]), "r"(b0),"r"(b1));
}

#define FKJ(F00,F01,F02,F10,F11,F12,F20,F21,F22,PX,PY,PZ,TH) do {              \
    float s_, c_; __sincosf((TH), &s_, &c_);                                   \
    tx += r00*(PX) + r01*(PY) + r02*(PZ);                                      \
    ty += r10*(PX) + r11*(PY) + r12*(PZ);                                      \
    tz += r20*(PX) + r21*(PY) + r22*(PZ);                                      \
    float A0 = r00*(F00) + r01*(F10) + r02*(F20);                              \
    float A1 = r10*(F00) + r11*(F10) + r12*(F20);                              \
    float A2 = r20*(F00) + r21*(F10) + r22*(F20);                              \
    float B0 = r00*(F01) + r01*(F11) + r02*(F21);                              \
    float B1 = r10*(F01) + r11*(F11) + r12*(F21);                              \
    float B2 = r20*(F01) + r21*(F11) + r22*(F21);                              \
    float C0 = r00*(F02) + r01*(F12) + r02*(F22);                              \
    float C1 = r10*(F02) + r11*(F12) + r12*(F22);                              \
    float C2v = r20*(F02) + r21*(F12) + r22*(F22);                             \
    r00 = c_*A0 + s_*B0;  r01 = c_*B0 - s_*A0;  r02 = C0;                      \
    r10 = c_*A1 + s_*B1;  r11 = c_*B1 - s_*A1;  r12 = C1;                      \
    r20 = c_*A2 + s_*B2;  r21 = c_*B2 - s_*A2;  r22 = C2v;                     \
} while (0)

static __device__ __forceinline__ void front_sample(
    int s, int it, const float* th, float vm,
    const float* __restrict__ tgt2d, const float* __restrict__ camK,
    const float* __restrict__ Rext,  const float* __restrict__ text,
    float* __restrict__ outAllKp, float* __restrict__ outKp,
    float* __restrict__ outTheta, u64* xp, int last)
{
    float kx[7], ky[7], kz[7];
    float r00=1.f,r01=0.f,r02=0.f, r10=0.f,r11=1.f,r12=0.f, r20=0.f,r21=0.f,r22=1.f;
    float tx=0.f, ty=0.f, tz=0.f;
    FKJ(1,0,0,  0,1,0,  0,0,1,   0.f,      0.f,     0.333f, th[0]);
    FKJ(1,0,0,  0,0,1,  0,-1,0,  0.f,      0.f,     0.f,    th[1]);
    kx[1]=tx; ky[1]=ty; kz[1]=tz;
    FKJ(1,0,0,  0,0,-1, 0,1,0,   0.f,     -0.316f,  0.f,    th[2]);
    kx[2]=tx; ky[2]=ty; kz[2]=tz;
    FKJ(1,0,0,  0,0,-1, 0,1,0,   0.0825f,  0.f,     0.f,    th[3]);
    kx[3]=tx; ky[3]=ty; kz[3]=tz;
    FKJ(1,0,0,  0,0,1,  0,-1,0, -0.0825f,  0.384f,  0.f,    th[4]);
    FKJ(1,0,0,  0,0,-1, 0,1,0,   0.f,      0.f,     0.f,    th[5]);
    kx[4]=tx; ky[4]=ty; kz[4]=tz;
    FKJ(1,0,0,  0,0,-1, 0,1,0,   0.088f,   0.f,     0.f,    th[6]);
    kx[5]=tx; ky[5]=ty; kz[5]=tz;
    kx[6]=tx + 0.107f*r02; ky[6]=ty + 0.107f*r12; kz[6]=tz + 0.107f*r22;
    kx[0]=0.f; ky[0]=0.f; kz[0]=0.f;
    {
        float* p = outAllKp + ((size_t)it * B_TOT + s) * 21;
#pragma unroll
        for (int k = 0; k < 7; k++) { p[3*k]=kx[k]; p[3*k+1]=ky[k]; p[3*k+2]=kz[k]; }
    }
    if (last) {
#pragma unroll
        for (int jj = 0; jj < 7; jj++) outTheta[(size_t)s*7 + jj] = th[jj];
        float* pkf = outKp + (size_t)s*21;
#pragma unroll
        for (int k = 0; k < 7; k++) { pkf[3*k]=kx[k]; pkf[3*k+1]=ky[k]; pkf[3*k+2]=kz[k]; }
        return;
    }
    float re[9], Kc[9], te[3];
#pragma unroll
    for (int i = 0; i < 9; i++) { re[i] = Rext[(size_t)s*9+i]; Kc[i] = camK[(size_t)s*9+i]; }
#pragma unroll
    for (int i = 0; i < 3; i++) te[i] = text[(size_t)s*3+i];
    float dmag[7];
#pragma unroll
    for (int k = 0; k < 7; k++) {
        float cxm = re[0]*kx[k] + re[1]*ky[k] + re[2]*kz[k] + te[0];
        float cym = re[3]*kx[k] + re[4]*ky[k] + re[5]*kz[k] + te[1];
        float czm = re[6]*kx[k] + re[7]*ky[k] + re[8]*kz[k] + te[2];
        float iz = 1.0f / fmaxf(czm, 1e-6f);
        float nx = cxm*iz, ny = cym*iz, nz = czm*iz;
        float u = Kc[0]*nx + Kc[1]*ny + Kc[2]*nz;
        float v = Kc[3]*nx + Kc[4]*ny + Kc[5]*nz;
        float du = (tgt2d[(size_t)s*14 + 2*k    ] - u) * vm;
        float dv = (tgt2d[(size_t)s*14 + 2*k + 1] - v) * vm;
        xp[k] = pk2(du, dv);
        dmag[k] = sqrtf(du*du + dv*dv);
    }
    xp[7]  = pk2(th[0], th[1]);   xp[8]  = pk2(th[2], th[3]);
    xp[9]  = pk2(th[4], th[5]);   xp[10] = pk2(th[6], dmag[0]);
    xp[11] = pk2(dmag[1], dmag[2]); xp[12] = pk2(dmag[3], dmag[4]);
    xp[13] = pk2(dmag[5], dmag[6]);
}

__global__ __launch_bounds__(THREADS,1)
void irm_kernel(const float* __restrict__ ang0,  const float* __restrict__ tgt2d,
                const float* __restrict__ camK,  const float* __restrict__ Rext,
                const float* __restrict__ text,  const int* __restrict__ vmask,
                const float* __restrict__ W1,    const float* __restrict__ b1,
                const float* __restrict__ g1,    const float* __restrict__ be1,
                const float* __restrict__ W2,    const float* __restrict__ b2,
                const float* __restrict__ g2,    const float* __restrict__ be2,
                const float* __restrict__ W3,    const float* __restrict__ b3,
                const float* __restrict__ slog,  float* __restrict__ out)
{
    extern __shared__ float smf[];
    char* const smc = (char*)smf;
    const uint32_t sbase = s2u(smc);
    const int tid = threadIdx.x;
    const int wid = tid >> 5, lane = tid & 31;

    // ================= weight preprocessing =================
    float* const W1P = smf + (W1P_O/4);
    for (int idx = tid; idx < 1792; idx += THREADS) {
        int j = idx & 127, p = idx >> 7;
        W1P[j*28 + p*2]     = W1[(2*p)  *128 + j];
        W1P[j*28 + p*2 + 1] = W1[(2*p+1)*128 + j];
    }
    if (tid < 128) smf[B1_O/4 + tid] = b1[tid];
    // W2 (g1-folded) -> bf16 hi/lo, [k][j] rows of 272 B
    for (int idx = tid; idx < 16384; idx += THREADS) {
        int k = idx >> 7, j = idx & 127;
        float v = g1[k] * W2[k*128 + j];
        __nv_bfloat16 h = __float2bfloat16(v);
        __nv_bfloat16 l = __float2bfloat16(v - __bfloat162float(h));
        *(__nv_bfloat16*)(smc + W2H_O + k*272 + j*2) = h;
        *(__nv_bfloat16*)(smc + W2L_O + k*272 + j*2) = l;
    }
    if (tid < 128) {
        float ga = 0.f, ca = 0.f;
        for (int k = 0; k < 128; k++) { float w = W2[k*128 + tid]; ga += g1[k]*w; ca += be1[k]*w; }
        ((float2*)(smc + G2C2_O))[tid] = make_float2(ga, ca + b2[tid]);
    }
    for (int idx = tid; idx < 512; idx += THREADS) {
        int k = idx & 127, p = idx >> 7;
        float gk = g2[k];
        int j0 = 2*p, j1 = 2*p + 1;
        smf[W3G_O/4 + k*8 + p*2]     = gk * W3[k*7 + j0];
        smf[W3G_O/4 + k*8 + p*2 + 1] = (j1 < 7) ? gk * W3[k*7 + j1] : 0.0f;
    }
    if (tid < 8) {
        float ga = 0.f, ca = 0.f;
        if (tid < 7) {
            for (int k = 0; k < 128; k++) { float w = W3[k*7 + tid]; ga += g2[k]*w; ca += be2[k]*w; }
            ca += b3[tid];
        }
        smf[G3_O/4 + tid] = ga;  smf[C3_O/4 + tid] = ca;
    }
    __syncthreads();

    // ================= per-thread sample =================
    const int s = blockIdx.x * THREADS + tid;
    float th[7];
#pragma unroll
    for (int j = 0; j < 7; j++) th[j] = ang0[s*7 + j];
    const float vm = (vmask[s] != 0) ? 1.0f : 0.0f;

    float* const outTheta = out;
    float* const outKp    = out + (size_t)B_TOT*7;
    float* const outAng   = out + (size_t)B_TOT*28;
    float* const outAllKp = out + (size_t)B_TOT*56;
#pragma unroll
    for (int j = 0; j < 7; j++) outAng[(size_t)s*7 + j] = th[j];

    // ldmatrix lane offsets (identical formula for A and B maps)
    const int lidx = lane >> 3, lr = lane & 7;
    const uint32_t frag_off = (uint32_t)(((lidx & 1)*8 + lr)*272 + (lidx >> 1)*16);
    const uint32_t aAddr0 = sbase + H1H_O + (uint32_t)(wid*32)*272 + frag_off;        // stripe 0
    const uint32_t aAddr1 = aAddr0 + 16u*272u;                                        // stripe 1
    const uint32_t bAddr  = sbase + W2H_O + frag_off;
    // H2 write coords
    const int dm  = lane >> 2;              // row within stripe (0..7)
    const int dj  = 2*(lane & 3);           // col offset within 8-wide tile

    for (int it = 0; it < 4; ++it) {
        u64 xp[14];
        const int last = (it == 3);
        front_sample(s, it, th, vm, tgt2d, camK, Rext, text, outAllKp, outKp, outTheta, xp, last);
        if (last) break;

        // ---------------- layer 1 scalar -> h1 (bf16 hi/lo to SMEM) ----------------
        float sum1 = 0.f, sq1 = 0.f;
        for (int j2o = 0; j2o < 16; j2o++) {
            uint32_t hq[4], lq[4];
#pragma unroll
            for (int u = 0; u < 4; u++) {
                const int j2 = 4*j2o + u;
                const ulonglong2* wa = (const ulonglong2*)(W1P + (2*j2)  *28);
                const ulonglong2* wb = (const ulonglong2*)(W1P + (2*j2+1)*28);
                u64 a0=0,a1=0,c0=0,c1=0;
#pragma unroll
                for (int q = 0; q < 7; q++) {
                    ulonglong2 va = wa[q], vb = wb[q];
                    a0 = ffma2(xp[2*q],   va.x, a0);
                    a1 = ffma2(xp[2*q+1], va.y, a1);
                    c0 = ffma2(xp[2*q],   vb.x, c0);
                    c1 = ffma2(xp[2*q+1], vb.y, c1);
                }
                float v0 = gelu_exact(red4(a0,a1) + smf[B1_O/4 + 2*j2]);
                float v1 = gelu_exact(red4(c0,c1) + smf[B1_O/4 + 2*j2 + 1]);
                sum1 += v0 + v1;  sq1 += v0*v0 + v1*v1;
                __nv_bfloat162 H = __floats2bfloat162_rn(v0, v1);
                float h0 = __low2float(H), h1f = __high2float(H);
                __nv_bfloat162 L = __floats2bfloat162_rn(v0 - h0, v1 - h1f);
                hq[u] = *(uint32_t*)&H;  lq[u] = *(uint32_t*)&L;
            }
            *(uint4*)(smc + H1H_O + tid*272 + j2o*16) = make_uint4(hq[0],hq[1],hq[2],hq[3]);
            *(uint4*)(smc + H1L_O + tid*272 + j2o*16) = make_uint4(lq[0],lq[1],lq[2],lq[3]);
        }
        float mu1 = sum1*(1.0f/128.0f);
        float rs1 = rsqrtf(sq1*(1.0f/128.0f) - mu1*mu1 + 1e-5f);
        float bco1 = rs1*mu1;
        __syncwarp();   // own warp's h1 rows visible for ldmatrix

        // ---------------- layer 2 via mma.sync (warp does its own 32 samples) ----------------
        float acc[2][16][4];
#pragma unroll
        for (int st = 0; st < 2; st++)
#pragma unroll
            for (int t = 0; t < 16; t++)
#pragma unroll
                for (int e = 0; e < 4; e++) acc[st][t][e] = 0.f;

        for (int ks = 0; ks < 8; ks++) {
            uint32_t ah[2][4], al[2][4];
            ldsm4(ah[0][0],ah[0][1],ah[0][2],ah[0][3], aAddr0 + ks*32);
            ldsm4(al[0][0],al[0][1],al[0][2],al[0][3], aAddr0 + ks*32 + (H1L_O - H1H_O));
            ldsm4(ah[1][0],ah[1][1],ah[1][2],ah[1][3], aAddr1 + ks*32);
            ldsm4(al[1][0],al[1][1],al[1][2],al[1][3], aAddr1 + ks*32 + (H1L_O - H1H_O));
#pragma unroll
            for (int jt2 = 0; jt2 < 8; jt2++) {
                uint32_t bh0,bh1,bh2,bh3, bl0,bl1,bl2,bl3;
                uint32_t ba = bAddr + (uint32_t)ks*16u*272u + (uint32_t)jt2*32u;
                ldsm4t(bh0,bh1,bh2,bh3, ba);
                ldsm4t(bl0,bl1,bl2,bl3, ba + (W2L_O - W2H_O));
#pragma unroll
                for (int st = 0; st < 2; st++) {
                    mma16816(acc[st][2*jt2],   ah[st], bh0, bh1);
                    mma16816(acc[st][2*jt2],   al[st], bh0, bh1);
                    mma16816(acc[st][2*jt2],   ah[st], bl0, bl1);
                    mma16816(acc[st][2*jt2+1], ah[st], bh2, bh3);
                    mma16816(acc[st][2*jt2+1], al[st], bh2, bh3);
                    mma16816(acc[st][2*jt2+1], ah[st], bl2, bl3);
                }
            }
        }
        __syncthreads();   // all warps done reading h1 before H2 overlays it

        // write H2 [chunk(j/4)][sample][4 f32]
#pragma unroll
        for (int st = 0; st < 2; st++) {
            const int m0 = wid*32 + st*16 + dm;
#pragma unroll
            for (int t = 0; t < 16; t++) {
                const int j0 = t*8 + dj;
                const uint32_t base = H2_O + (uint32_t)(j0 >> 2)*4096u + ((j0 & 3) << 2);
                *(float2*)(smc + base + m0*16)       = make_float2(acc[st][t][0], acc[st][t][1]);
                *(float2*)(smc + base + (m0+8)*16)   = make_float2(acc[st][t][2], acc[st][t][3]);
            }
        }
        __syncwarp();   // own warp wrote own samples' chunks

        // ---------------- readback: LN1-fold -> GELU -> LN2 stats + layer 3 ----------------
        float sum2 = 0.f, sq2 = 0.f;
        u64 S0=0,S1=0,S2=0,S3=0;
        const float2* const G2C2 = (const float2*)(smc + G2C2_O);
        for (int c = 0; c < 32; c++) {
            float4 t4 = *(const float4*)(smc + H2_O + c*4096 + tid*16);
            float tv[4] = {t4.x, t4.y, t4.z, t4.w};
#pragma unroll
            for (int e = 0; e < 4; e++) {
                const int row = 4*c + e;
                float2 gc = G2C2[row];
                float v = gelu_exact(rs1*tv[e] - bco1*gc.x + gc.y);
                sum2 += v; sq2 += v*v;
                const ulonglong2* w3r = (const ulonglong2*)(smf + W3G_O/4 + row*8);
                ulonglong2 wa3 = w3r[0], wb3 = w3r[1];
                u64 v2 = pk2(v,v);
                S0 = ffma2(v2, wa3.x, S0);  S1 = ffma2(v2, wa3.y, S1);
                S2 = ffma2(v2, wb3.x, S2);  S3 = ffma2(v2, wb3.y, S3);
            }
        }
        float mu2 = sum2*(1.0f/128.0f);
        float rs2 = rsqrtf(sq2*(1.0f/128.0f) - mu2*mu2 + 1e-5f);
        float bco2 = rs2*mu2;
        float sv[8];
        upk2(S0, sv[0], sv[1]); upk2(S1, sv[2], sv[3]);
        upk2(S2, sv[4], sv[5]); upk2(S3, sv[6], sv[7]);

        const float ssi = 1.0f/(1.0f + expf(-slog[it]));
        const float LO[7] = {-2.8973f,-1.7628f,-2.8973f,-3.0718f,-2.8973f,-0.0175f,-2.8973f};
        const float HI[7] = { 2.8973f, 1.7628f, 2.8973f,-0.0698f, 2.8973f, 3.7525f, 2.8973f};
#pragma unroll
        for (int jj = 0; jj < 7; jj++) {
            float dl = rs2*sv[jj] - bco2*smf[G3_O/4 + jj] + smf[C3_O/4 + jj];
            th[jj] = fminf(fmaxf(th[jj] + ssi*dl, LO[jj]), HI[jj]);
        }
        float* pa = outAng + ((size_t)(it+1)*B_TOT + s)*7;
#pragma unroll
        for (int jj = 0; jj < 7; jj++) pa[jj] = th[jj];

        __syncthreads();   // H2 reads done before next iter's h1 writes
    }
}

extern "C" void kernel_launch(void* const* d_in, const int* in_sizes, int n_in,
                              void* d_out, int out_size) {
    (void)in_sizes; (void)n_in; (void)out_size;
    cudaFuncSetAttribute(irm_kernel, cudaFuncAttributeMaxDynamicSharedMemorySize, SMEM_BYTES);
    irm_kernel<<<CTAS, THREADS, SMEM_BYTES>>>(
        (const float*)d_in[0], (const float*)d_in[1], (const float*)d_in[2],
        (const float*)d_in[4], (const float*)d_in[5], (const int*)d_in[6],
        (const float*)d_in[7],  (const float*)d_in[8],
        (const float*)d_in[9],  (const float*)d_in[10],
        (const float*)d_in[11], (const float*)d_in[12],
        (const float*)d_in[13], (const float*)d_in[14],
        (const float*)d_in[15], (const float*)d_in[16],
        (const float*)d_in[17],
        (float*)d_out);
}

// round 12
// speedup vs baseline: 1.9035x; 1.0548x over previous
#include <cuda_runtime.h>
#include <cuda_bf16.h>
#include <math.h>
#include <stdint.h>

#define B_TOT   262144
#define THREADS 256
#define CTAS    (B_TOT/THREADS)   // 1024

// ---- SMEM layout (bytes) ----
#define W2H_O   0        // W2 g1-folded hi: 128 rows x 272 B
#define W2L_O   34816    // W2 lo
#define W1H_O   69632    // W1 (+b1 row 28) hi: 32 rows x 272 B
#define W1L_O   78336    // W1 lo
#define W3G_O   87040    // float[128*8] g2-folded W3
#define G2C2_O  91136    // float2[128]
#define G3_O    92160    // 8 f
#define C3_O    92192    // 8 f
#define H1H_O   92224    // h1 hi: 256 rows x 272 B (x staging + H2 overlay here)
#define H1L_O   161856   // h1 lo
#define SMEM_BYTES 231488
#define H2_O    H1H_O    // overlay: 32 chunks x 4096 B (f32 [chunk][sample][4])

typedef unsigned long long u64;

static __device__ __forceinline__ u64 pk2(float lo, float hi) {
    u64 r; asm("mov.b64 %0,{%1,%2};" : "=l"(r) : "f"(lo), "f"(hi)); return r;
}
static __device__ __forceinline__ void upk2(u64 v, float &lo, float &hi) {
    asm("mov.b64 {%0,%1},%2;" : "=f"(lo), "=f"(hi) : "l"(v));
}
static __device__ __forceinline__ u64 ffma2(u64 a, u64 b, u64 c) {
    u64 d; asm("fma.rn.f32x2 %0,%1,%2,%3;" : "=l"(d) : "l"(a), "l"(b), "l"(c)); return d;
}
static __device__ __forceinline__ u64 fadd2(u64 a, u64 b) {
    u64 d; asm("add.rn.f32x2 %0,%1,%2;" : "=l"(d) : "l"(a), "l"(b)); return d;
}
static __device__ __forceinline__ float gelu_exact(float x) {
    return 0.5f * x * (1.0f + erff(x * 0.70710678118654752f));
}
static __device__ __forceinline__ uint32_t s2u(const void* p){
    uint32_t a; asm("{ .reg .u64 t; cvta.to.shared.u64 t, %1; cvt.u32.u64 %0, t; }":"=r"(a):"l"(p)); return a;
}
static __device__ __forceinline__ void ldsm4(uint32_t& r0,uint32_t& r1,uint32_t& r2,uint32_t& r3, uint32_t a){
    asm volatile("ldmatrix.sync.aligned.m8n8.x4.shared.b16 {%0,%1,%2,%3}, [%4];"
        : "=r"(r0),"=r"(r1),"=r"(r2),"=r"(r3) : "r"(a));
}
static __device__ __forceinline__ void ldsm4t(uint32_t& r0,uint32_t& r1,uint32_t& r2,uint32_t& r3, uint32_t a){
    asm volatile("ldmatrix.sync.aligned.m8n8.x4.trans.shared.b16 {%0,%1,%2,%3}, [%4];"
        : "=r"(r0),"=r"(r1),"=r"(r2),"=r"(r3) : "r"(a));
}
static __device__ __forceinline__ void mma16816(float* d, const uint32_t* a, uint32_t b0, uint32_t b1){
    asm volatile("mma.sync.aligned.m16n8k16.row.col.f32.bf16.bf16.f32 "
        "{%0,%1,%2,%3}, {%4,%5,%6,%7}, {%8,%9}, {%0,%1,%2,%3};"
        : "+f"(d[0]),"+f"(d[1]),"+f"(d[2]),"+f"(d[3])
        : "r"(a[0]),"r"(a[1]),"r"(a[2]),"r"(a[3]), "r"(b0),"r"(b1));
}

#define FKJ(F00,F01,F02,F10,F11,F12,F20,F21,F22,PX,PY,PZ,TH) do {              \
    float s_, c_; __sincosf((TH), &s_, &c_);                                   \
    tx += r00*(PX) + r01*(PY) + r02*(PZ);                                      \
    ty += r10*(PX) + r11*(PY) + r12*(PZ);                                      \
    tz += r20*(PX) + r21*(PY) + r22*(PZ);                                      \
    float A0 = r00*(F00) + r01*(F10) + r02*(F20);                              \
    float A1 = r10*(F00) + r11*(F10) + r12*(F20);                              \
    float A2 = r20*(F00) + r21*(F10) + r22*(F20);                              \
    float B0 = r00*(F01) + r01*(F11) + r02*(F21);                              \
    float B1 = r10*(F01) + r11*(F11) + r12*(F21);                              \
    float B2 = r20*(F01) + r21*(F11) + r22*(F21);                              \
    float C0 = r00*(F02) + r01*(F12) + r02*(F22);                              \
    float C1 = r10*(F02) + r11*(F12) + r12*(F22);                              \
    float C2v = r20*(F02) + r21*(F12) + r22*(F22);                             \
    r00 = c_*A0 + s_*B0;  r01 = c_*B0 - s_*A0;  r02 = C0;                      \
    r10 = c_*A1 + s_*B1;  r11 = c_*B1 - s_*A1;  r12 = C1;                      \
    r20 = c_*A2 + s_*B2;  r21 = c_*B2 - s_*A2;  r22 = C2v;                     \
} while (0)

static __device__ __forceinline__ void front_sample(
    int s, int it, const float* th, float vm,
    const float* __restrict__ tgt2d, const float* __restrict__ camK,
    const float* __restrict__ Rext,  const float* __restrict__ text,
    float* __restrict__ outAllKp, float* __restrict__ outKp,
    float* __restrict__ outTheta, u64* xp, int last)
{
    float kx[7], ky[7], kz[7];
    float r00=1.f,r01=0.f,r02=0.f, r10=0.f,r11=1.f,r12=0.f, r20=0.f,r21=0.f,r22=1.f;
    float tx=0.f, ty=0.f, tz=0.f;
    FKJ(1,0,0,  0,1,0,  0,0,1,   0.f,      0.f,     0.333f, th[0]);
    FKJ(1,0,0,  0,0,1,  0,-1,0,  0.f,      0.f,     0.f,    th[1]);
    kx[1]=tx; ky[1]=ty; kz[1]=tz;
    FKJ(1,0,0,  0,0,-1, 0,1,0,   0.f,     -0.316f,  0.f,    th[2]);
    kx[2]=tx; ky[2]=ty; kz[2]=tz;
    FKJ(1,0,0,  0,0,-1, 0,1,0,   0.0825f,  0.f,     0.f,    th[3]);
    kx[3]=tx; ky[3]=ty; kz[3]=tz;
    FKJ(1,0,0,  0,0,1,  0,-1,0, -0.0825f,  0.384f,  0.f,    th[4]);
    FKJ(1,0,0,  0,0,-1, 0,1,0,   0.f,      0.f,     0.f,    th[5]);
    kx[4]=tx; ky[4]=ty; kz[4]=tz;
    FKJ(1,0,0,  0,0,-1, 0,1,0,   0.088f,   0.f,     0.f,    th[6]);
    kx[5]=tx; ky[5]=ty; kz[5]=tz;
    kx[6]=tx + 0.107f*r02; ky[6]=ty + 0.107f*r12; kz[6]=tz + 0.107f*r22;
    kx[0]=0.f; ky[0]=0.f; kz[0]=0.f;
    {
        float* p = outAllKp + ((size_t)it * B_TOT + s) * 21;
#pragma unroll
        for (int k = 0; k < 7; k++) { p[3*k]=kx[k]; p[3*k+1]=ky[k]; p[3*k+2]=kz[k]; }
    }
    if (last) {
#pragma unroll
        for (int jj = 0; jj < 7; jj++) outTheta[(size_t)s*7 + jj] = th[jj];
        float* pkf = outKp + (size_t)s*21;
#pragma unroll
        for (int k = 0; k < 7; k++) { pkf[3*k]=kx[k]; pkf[3*k+1]=ky[k]; pkf[3*k+2]=kz[k]; }
        return;
    }
    float re[9], Kc[9], te[3];
#pragma unroll
    for (int i = 0; i < 9; i++) { re[i] = Rext[(size_t)s*9+i]; Kc[i] = camK[(size_t)s*9+i]; }
#pragma unroll
    for (int i = 0; i < 3; i++) te[i] = text[(size_t)s*3+i];
    float dmag[7];
#pragma unroll
    for (int k = 0; k < 7; k++) {
        float cxm = re[0]*kx[k] + re[1]*ky[k] + re[2]*kz[k] + te[0];
        float cym = re[3]*kx[k] + re[4]*ky[k] + re[5]*kz[k] + te[1];
        float czm = re[6]*kx[k] + re[7]*ky[k] + re[8]*kz[k] + te[2];
        float iz = 1.0f / fmaxf(czm, 1e-6f);
        float nx = cxm*iz, ny = cym*iz, nz = czm*iz;
        float u = Kc[0]*nx + Kc[1]*ny + Kc[2]*nz;
        float v = Kc[3]*nx + Kc[4]*ny + Kc[5]*nz;
        float du = (tgt2d[(size_t)s*14 + 2*k    ] - u) * vm;
        float dv = (tgt2d[(size_t)s*14 + 2*k + 1] - v) * vm;
        xp[k] = pk2(du, dv);
        dmag[k] = sqrtf(du*du + dv*dv);
    }
    xp[7]  = pk2(th[0], th[1]);   xp[8]  = pk2(th[2], th[3]);
    xp[9]  = pk2(th[4], th[5]);   xp[10] = pk2(th[6], dmag[0]);
    xp[11] = pk2(dmag[1], dmag[2]); xp[12] = pk2(dmag[3], dmag[4]);
    xp[13] = pk2(dmag[5], dmag[6]);
}

__global__ __launch_bounds__(THREADS,1)
void irm_kernel(const float* __restrict__ ang0,  const float* __restrict__ tgt2d,
                const float* __restrict__ camK,  const float* __restrict__ Rext,
                const float* __restrict__ text,  const int* __restrict__ vmask,
                const float* __restrict__ W1,    const float* __restrict__ b1,
                const float* __restrict__ g1,    const float* __restrict__ be1,
                const float* __restrict__ W2,    const float* __restrict__ b2,
                const float* __restrict__ g2,    const float* __restrict__ be2,
                const float* __restrict__ W3,    const float* __restrict__ b3,
                const float* __restrict__ slog,  float* __restrict__ out)
{
    extern __shared__ float smf[];
    char* const smc = (char*)smf;
    const uint32_t sbase = s2u(smc);
    const int tid = threadIdx.x;
    const int wid = tid >> 5, lane = tid & 31;

    // ================= weight preprocessing =================
    // W2 (g1-folded) bf16 hi/lo, rows of 272 B
    for (int idx = tid; idx < 16384; idx += THREADS) {
        int k = idx >> 7, j = idx & 127;
        float v = g1[k] * W2[k*128 + j];
        __nv_bfloat16 h = __float2bfloat16(v);
        __nv_bfloat16 l = __float2bfloat16(v - __bfloat162float(h));
        *(__nv_bfloat16*)(smc + W2H_O + k*272 + j*2) = h;
        *(__nv_bfloat16*)(smc + W2L_O + k*272 + j*2) = l;
    }
    // W1 bf16 hi/lo: rows 0-27 = W1, row 28 = b1 (bias fold), rows 29-31 = 0
    for (int idx = tid; idx < 4096; idx += THREADS) {
        int k = idx >> 7, j = idx & 127;
        float v = (k < 28) ? W1[k*128 + j] : ((k == 28) ? b1[j] : 0.f);
        __nv_bfloat16 h = __float2bfloat16(v);
        __nv_bfloat16 l = __float2bfloat16(v - __bfloat162float(h));
        *(__nv_bfloat16*)(smc + W1H_O + k*272 + j*2) = h;
        *(__nv_bfloat16*)(smc + W1L_O + k*272 + j*2) = l;
    }
    if (tid < 128) {
        float ga = 0.f, ca = 0.f;
        for (int k = 0; k < 128; k++) { float w = W2[k*128 + tid]; ga += g1[k]*w; ca += be1[k]*w; }
        ((float2*)(smc + G2C2_O))[tid] = make_float2(ga, ca + b2[tid]);
    }
    for (int idx = tid; idx < 512; idx += THREADS) {
        int k = idx & 127, p = idx >> 7;
        float gk = g2[k];
        int j0 = 2*p, j1 = 2*p + 1;
        smf[W3G_O/4 + k*8 + p*2]     = gk * W3[k*7 + j0];
        smf[W3G_O/4 + k*8 + p*2 + 1] = (j1 < 7) ? gk * W3[k*7 + j1] : 0.0f;
    }
    if (tid < 8) {
        float ga = 0.f, ca = 0.f;
        if (tid < 7) {
            for (int k = 0; k < 128; k++) { float w = W3[k*7 + tid]; ga += g2[k]*w; ca += be2[k]*w; }
            ca += b3[tid];
        }
        smf[G3_O/4 + tid] = ga;  smf[C3_O/4 + tid] = ca;
    }
    __syncthreads();

    // ================= per-thread sample =================
    const int s = blockIdx.x * THREADS + tid;
    float th[7];
#pragma unroll
    for (int j = 0; j < 7; j++) th[j] = ang0[s*7 + j];
    const float vm = (vmask[s] != 0) ? 1.0f : 0.0f;

    float* const outTheta = out;
    float* const outKp    = out + (size_t)B_TOT*7;
    float* const outAng   = out + (size_t)B_TOT*28;
    float* const outAllKp = out + (size_t)B_TOT*56;
#pragma unroll
    for (int j = 0; j < 7; j++) outAng[(size_t)s*7 + j] = th[j];

    // fragment geometry
    const int lidx = lane >> 3, lr = lane & 7;
    const int dm = lane >> 2, q = lane & 3;
    const uint32_t frag272 = (uint32_t)(((lidx & 1)*8 + lr)*272 + (lidx >> 1)*16);
    const uint32_t frag80  = (uint32_t)(((lidx & 1)*8 + lr)*80  + (lidx >> 1)*16);
    const uint32_t wslot   = (uint32_t)wid * 8704u;
    const uint32_t xAddrH  = sbase + H1H_O + wslot + frag80;   // x hi (stripe +1280, ks +32)
    const uint32_t aAddr0  = sbase + H1H_O + wslot + frag272;  // h1 A for MMA2
    const uint32_t aAddr1  = aAddr0 + 16u*272u;
    const uint32_t w1Addr  = sbase + W1H_O + frag272;
    const uint32_t bAddr   = sbase + W2H_O + frag272;
    const int dj  = 2*q;

    for (int it = 0; it < 4; ++it) {
        u64 xp[14];
        const int last = (it == 3);
        front_sample(s, it, th, vm, tgt2d, camK, Rext, text, outAllKp, outKp, outTheta, xp, last);
        if (last) break;

        // ---------------- stage x (bf16 hi/lo) into per-warp slot ----------------
        {
            uint32_t xh[16], xl[16];
#pragma unroll
            for (int c = 0; c < 14; c++) {
                float v0, v1; upk2(xp[c], v0, v1);
                __nv_bfloat162 H = __floats2bfloat162_rn(v0, v1);
                __nv_bfloat162 L = __floats2bfloat162_rn(v0 - __low2float(H), v1 - __high2float(H));
                xh[c] = *(uint32_t*)&H;  xl[c] = *(uint32_t*)&L;
            }
            __nv_bfloat162 Hb = __floats2bfloat162_rn(1.0f, 0.0f);
            xh[14] = *(uint32_t*)&Hb;  xl[14] = 0u;  xh[15] = 0u;  xl[15] = 0u;
            char* px = smc + H1H_O + wslot + lane*80;
            *(uint4*)(px)      = make_uint4(xh[0],xh[1],xh[2],xh[3]);
            *(uint4*)(px + 16) = make_uint4(xh[4],xh[5],xh[6],xh[7]);
            *(uint4*)(px + 32) = make_uint4(xh[8],xh[9],xh[10],xh[11]);
            *(uint4*)(px + 48) = make_uint4(xh[12],xh[13],xh[14],xh[15]);
            char* pl = px + (H1L_O - H1H_O);
            *(uint4*)(pl)      = make_uint4(xl[0],xl[1],xl[2],xl[3]);
            *(uint4*)(pl + 16) = make_uint4(xl[4],xl[5],xl[6],xl[7]);
            *(uint4*)(pl + 32) = make_uint4(xl[8],xl[9],xl[10],xl[11]);
            *(uint4*)(pl + 48) = make_uint4(xl[12],xl[13],xl[14],xl[15]);
        }
        __syncwarp();

        // ---------------- MMA1: h1pre = x @ W1 (+bias row) ----------------
        uint32_t a1h[2][2][4], a1l[2][2][4];
#pragma unroll
        for (int st = 0; st < 2; st++)
#pragma unroll
            for (int ks = 0; ks < 2; ks++) {
                uint32_t base = xAddrH + st*1280 + ks*32;
                ldsm4(a1h[st][ks][0],a1h[st][ks][1],a1h[st][ks][2],a1h[st][ks][3], base);
                ldsm4(a1l[st][ks][0],a1l[st][ks][1],a1l[st][ks][2],a1l[st][ks][3], base + (H1L_O - H1H_O));
            }

        u64 sP[2][2] = {{0,0},{0,0}}, qP[2][2] = {{0,0},{0,0}};
        float rs1v[2][2], bc1v[2][2];

        for (int nh = 0; nh < 2; nh++) {
            float acc1[2][8][4];
#pragma unroll
            for (int st2 = 0; st2 < 2; st2++)
#pragma unroll
                for (int t = 0; t < 8; t++)
#pragma unroll
                    for (int e = 0; e < 4; e++) acc1[st2][t][e] = 0.f;
#pragma unroll
            for (int ks = 0; ks < 2; ks++)
#pragma unroll
                for (int gl = 0; gl < 4; gl++) {
                    uint32_t ba = w1Addr + (uint32_t)ks*4352u + (uint32_t)(nh*4+gl)*32u;
                    uint32_t bh0,bh1,bh2,bh3, bl0,bl1,bl2,bl3;
                    ldsm4t(bh0,bh1,bh2,bh3, ba);
                    ldsm4t(bl0,bl1,bl2,bl3, ba + (W1L_O - W1H_O));
#pragma unroll
                    for (int st2 = 0; st2 < 2; st2++) {
                        mma16816(acc1[st2][2*gl],   a1h[st2][ks], bh0, bh1);
                        mma16816(acc1[st2][2*gl],   a1l[st2][ks], bh0, bh1);
                        mma16816(acc1[st2][2*gl],   a1h[st2][ks], bl0, bl1);
                        mma16816(acc1[st2][2*gl+1], a1h[st2][ks], bh2, bh3);
                        mma16816(acc1[st2][2*gl+1], a1l[st2][ks], bh2, bh3);
                        mma16816(acc1[st2][2*gl+1], a1h[st2][ks], bl2, bl3);
                    }
                }
            // epi1 on fragments: GELU, LN1 stats, h1 -> SMEM (bf16 hi/lo)
#pragma unroll
            for (int st2 = 0; st2 < 2; st2++)
#pragma unroll
                for (int t = 0; t < 8; t++) {
                    float v0 = gelu_exact(acc1[st2][t][0]);
                    float v1 = gelu_exact(acc1[st2][t][1]);
                    float v2 = gelu_exact(acc1[st2][t][2]);
                    float v3 = gelu_exact(acc1[st2][t][3]);
                    u64 p01 = pk2(v0,v1), p23 = pk2(v2,v3);
                    sP[st2][0] = fadd2(sP[st2][0], p01);
                    qP[st2][0] = ffma2(p01, p01, qP[st2][0]);
                    sP[st2][1] = fadd2(sP[st2][1], p23);
                    qP[st2][1] = ffma2(p23, p23, qP[st2][1]);
                    __nv_bfloat162 H0 = __floats2bfloat162_rn(v0, v1);
                    __nv_bfloat162 L0 = __floats2bfloat162_rn(v0 - __low2float(H0), v1 - __high2float(H0));
                    __nv_bfloat162 H1 = __floats2bfloat162_rn(v2, v3);
                    __nv_bfloat162 L1 = __floats2bfloat162_rn(v2 - __low2float(H1), v3 - __high2float(H1));
                    uint32_t colb = (uint32_t)(((nh*8 + t)*8 + dj)*2);
                    char* r0p = smc + H1H_O + wslot + (uint32_t)(st2*16 + dm)*272u + colb;
                    char* r1p = smc + H1H_O + wslot + (uint32_t)(st2*16 + dm + 8)*272u + colb;
                    *(uint32_t*)r0p = *(uint32_t*)&H0;
                    *(uint32_t*)r1p = *(uint32_t*)&H1;
                    *(uint32_t*)(r0p + (H1L_O - H1H_O)) = *(uint32_t*)&L0;
                    *(uint32_t*)(r1p + (H1L_O - H1H_O)) = *(uint32_t*)&L1;
                }
        }
        __syncwarp();

        // LN1 stats finalize (4-lane row groups) + broadcast to sample threads
#pragma unroll
        for (int st2 = 0; st2 < 2; st2++)
#pragma unroll
            for (int h = 0; h < 2; h++) {
                float a, b; upk2(sP[st2][h], a, b); float sum = a + b;
                upk2(qP[st2][h], a, b); float sq = a + b;
                sum += __shfl_xor_sync(0xFFFFFFFFu, sum, 1);
                sum += __shfl_xor_sync(0xFFFFFFFFu, sum, 2);
                sq  += __shfl_xor_sync(0xFFFFFFFFu, sq, 1);
                sq  += __shfl_xor_sync(0xFFFFFFFFu, sq, 2);
                float mu = sum * (1.0f/128.0f);
                float rs = rsqrtf(sq*(1.0f/128.0f) - mu*mu + 1e-5f);
                rs1v[st2][h] = rs;  bc1v[st2][h] = rs*mu;
            }
        float rs1 = 0.f, bco1 = 0.f;
        {
            const int st_s = lane >> 4, h_s = (lane >> 3) & 1, src = (lane & 7)*4;
#pragma unroll
            for (int st2 = 0; st2 < 2; st2++)
#pragma unroll
                for (int h = 0; h < 2; h++) {
                    float tr = __shfl_sync(0xFFFFFFFFu, rs1v[st2][h], src);
                    float tb = __shfl_sync(0xFFFFFFFFu, bc1v[st2][h], src);
                    if (st2 == st_s && h == h_s) { rs1 = tr; bco1 = tb; }
                }
        }

        // ---------------- layer 2 via mma.sync (R11, unchanged) ----------------
        float acc[2][16][4];
#pragma unroll
        for (int st2 = 0; st2 < 2; st2++)
#pragma unroll
            for (int t = 0; t < 16; t++)
#pragma unroll
                for (int e = 0; e < 4; e++) acc[st2][t][e] = 0.f;

        for (int ks = 0; ks < 8; ks++) {
            uint32_t ah[2][4], al[2][4];
            ldsm4(ah[0][0],ah[0][1],ah[0][2],ah[0][3], aAddr0 + ks*32);
            ldsm4(al[0][0],al[0][1],al[0][2],al[0][3], aAddr0 + ks*32 + (H1L_O - H1H_O));
            ldsm4(ah[1][0],ah[1][1],ah[1][2],ah[1][3], aAddr1 + ks*32);
            ldsm4(al[1][0],al[1][1],al[1][2],al[1][3], aAddr1 + ks*32 + (H1L_O - H1H_O));
#pragma unroll
            for (int jt2 = 0; jt2 < 8; jt2++) {
                uint32_t bh0,bh1,bh2,bh3, bl0,bl1,bl2,bl3;
                uint32_t ba = bAddr + (uint32_t)ks*16u*272u + (uint32_t)jt2*32u;
                ldsm4t(bh0,bh1,bh2,bh3, ba);
                ldsm4t(bl0,bl1,bl2,bl3, ba + (W2L_O - W2H_O));
#pragma unroll
                for (int st2 = 0; st2 < 2; st2++) {
                    mma16816(acc[st2][2*jt2],   ah[st2], bh0, bh1);
                    mma16816(acc[st2][2*jt2],   al[st2], bh0, bh1);
                    mma16816(acc[st2][2*jt2],   ah[st2], bl0, bl1);
                    mma16816(acc[st2][2*jt2+1], ah[st2], bh2, bh3);
                    mma16816(acc[st2][2*jt2+1], al[st2], bh2, bh3);
                    mma16816(acc[st2][2*jt2+1], ah[st2], bl2, bl3);
                }
            }
        }
        __syncthreads();   // all warps done with h1/x before H2 overlays region

        // write H2 [chunk(j/4)][sample][4 f32]
#pragma unroll
        for (int st2 = 0; st2 < 2; st2++) {
            const int m0 = wid*32 + st2*16 + dm;
#pragma unroll
            for (int t = 0; t < 16; t++) {
                const int j0 = t*8 + dj;
                const uint32_t base = H2_O + (uint32_t)(j0 >> 2)*4096u + ((j0 & 3) << 2);
                *(float2*)(smc + base + m0*16)       = make_float2(acc[st2][t][0], acc[st2][t][1]);
                *(float2*)(smc + base + (m0+8)*16)   = make_float2(acc[st2][t][2], acc[st2][t][3]);
            }
        }
        __syncwarp();

        // ---------------- readback: LN1-fold -> GELU -> LN2 stats + layer 3 ----------------
        float sum2 = 0.f, sq2 = 0.f;
        u64 S0=0,S1=0,S2=0,S3=0;
        const float2* const G2C2 = (const float2*)(smc + G2C2_O);
        for (int c = 0; c < 32; c++) {
            float4 t4 = *(const float4*)(smc + H2_O + c*4096 + tid*16);
            float tv[4] = {t4.x, t4.y, t4.z, t4.w};
#pragma unroll
            for (int e = 0; e < 4; e++) {
                const int row = 4*c + e;
                float2 gc = G2C2[row];
                float v = gelu_exact(rs1*tv[e] - bco1*gc.x + gc.y);
                sum2 += v; sq2 += v*v;
                const ulonglong2* w3r = (const ulonglong2*)(smf + W3G_O/4 + row*8);
                ulonglong2 wa3 = w3r[0], wb3 = w3r[1];
                u64 v2 = pk2(v,v);
                S0 = ffma2(v2, wa3.x, S0);  S1 = ffma2(v2, wa3.y, S1);
                S2 = ffma2(v2, wb3.x, S2);  S3 = ffma2(v2, wb3.y, S3);
            }
        }
        float mu2 = sum2*(1.0f/128.0f);
        float rs2 = rsqrtf(sq2*(1.0f/128.0f) - mu2*mu2 + 1e-5f);
        float bco2 = rs2*mu2;
        float sv[8];
        upk2(S0, sv[0], sv[1]); upk2(S1, sv[2], sv[3]);
        upk2(S2, sv[4], sv[5]); upk2(S3, sv[6], sv[7]);

        const float ssi = 1.0f/(1.0f + expf(-slog[it]));
        const float LO[7] = {-2.8973f,-1.7628f,-2.8973f,-3.0718f,-2.8973f,-0.0175f,-2.8973f};
        const float HI[7] = { 2.8973f, 1.7628f, 2.8973f,-0.0698f, 2.8973f, 3.7525f, 2.8973f};
#pragma unroll
        for (int jj = 0; jj < 7; jj++) {
            float dl = rs2*sv[jj] - bco2*smf[G3_O/4 + jj] + smf[C3_O/4 + jj];
            th[jj] = fminf(fmaxf(th[jj] + ssi*dl, LO[jj]), HI[jj]);
        }
        float* pa = outAng + ((size_t)(it+1)*B_TOT + s)*7;
#pragma unroll
        for (int jj = 0; jj < 7; jj++) pa[jj] = th[jj];

        __syncthreads();   // H2 reads done before next iter's x/h1 writes
    }
}

extern "C" void kernel_launch(void* const* d_in, const int* in_sizes, int n_in,
                              void* d_out, int out_size) {
    (void)in_sizes; (void)n_in; (void)out_size;
    cudaFuncSetAttribute(irm_kernel, cudaFuncAttributeMaxDynamicSharedMemorySize, SMEM_BYTES);
    irm_kernel<<<CTAS, THREADS, SMEM_BYTES>>>(
        (const float*)d_in[0], (const float*)d_in[1], (const float*)d_in[2],
        (const float*)d_in[4], (const float*)d_in[5], (const int*)d_in[6],
        (const float*)d_in[7],  (const float*)d_in[8],
        (const float*)d_in[9],  (const float*)d_in[10],
        (const float*)d_in[11], (const float*)d_in[12],
        (const float*)d_in[13], (const float*)d_in[14],
        (const float*)d_in[15], (const float*)d_in[16],
        (const float*)d_in[17],
        (float*)d_out);
}